// round 1
// baseline (speedup 1.0000x reference)
#include <cuda_runtime.h>

#define DH 96
#define DE 32
#define NMAX 50000

// Scratch (static __device__ arrays — allocation-free per harness rules)
__device__ float    g_XM[NMAX * DH];
__device__ float    g_XR[NMAX * DH];
__device__ float    g_C1[NMAX * DH];
__device__ unsigned g_AGG[NMAX * DH];

#define SENT 0x007FFFFFu  // enc(-inf)

__device__ __forceinline__ unsigned enc(float f) {
    unsigned u = __float_as_uint(f);
    return (u & 0x80000000u) ? ~u : (u | 0x80000000u);
}
__device__ __forceinline__ float dec(unsigned u) {
    return __uint_as_float((u & 0x80000000u) ? (u & 0x7FFFFFFFu) : ~u);
}

__global__ void init_agg(int n96) {
    int i = blockIdx.x * blockDim.x + threadIdx.x;
    int stride = gridDim.x * blockDim.x;
    for (; i < n96; i += stride) g_AGG[i] = SENT;
}

// Computes XM = in @ Wm  and  XR = in @ Wr + b   (both [n,96])
// blockDim = (96, 4). Dynamic smem: 2*96*96 floats (both W matrices).
extern __shared__ float smem_dyn[];
__global__ void node_gemm(const float* __restrict__ in,
                          const float* __restrict__ Wm,
                          const float* __restrict__ Wr,
                          const float* __restrict__ b,
                          float* __restrict__ XM,
                          float* __restrict__ XR,
                          int n) {
    float* Wms = smem_dyn;            // [96*96], layout [k][c]
    float* Wrs = smem_dyn + DH * DH;  // [96*96]
    __shared__ float xs[4][DH];
    __shared__ float bs[DH];

    int tid = threadIdx.y * blockDim.x + threadIdx.x;  // 0..383
    for (int i = tid; i < DH * DH; i += 384) { Wms[i] = Wm[i]; Wrs[i] = Wr[i]; }
    if (tid < DH) bs[tid] = b[tid];
    __syncthreads();

    int tx = threadIdx.x, ty = threadIdx.y;
    int ngroups = (n + 3) >> 2;
    for (int g = blockIdx.x; g < ngroups; g += gridDim.x) {
        int row0 = g * 4;
        __syncthreads();
        {
            int r = tid / DH, k = tid % DH;
            int row = row0 + r;
            xs[r][k] = (row < n) ? in[(size_t)row * DH + k] : 0.f;
        }
        __syncthreads();
        int row = row0 + ty;
        if (row < n) {
            float am = 0.f, ar = 0.f;
#pragma unroll 8
            for (int k = 0; k < DH; k++) {
                float xv = xs[ty][k];
                am = fmaf(xv, Wms[k * DH + tx], am);
                ar = fmaf(xv, Wrs[k * DH + tx], ar);
            }
            XM[(size_t)row * DH + tx] = am;
            XR[(size_t)row * DH + tx] = ar + bs[tx];
        }
    }
}

// One warp per edge: msg[c] = XM[src][c] + sum_k ea[e][k]*We[k][c],
// then atomicMax (monotone-uint) into g_AGG[dst][c].  96 ch = 3 per lane.
__global__ void edge_scatter(const float* __restrict__ XM,
                             const float* __restrict__ ea,
                             const float* __restrict__ We,
                             const int* __restrict__ src,
                             const int* __restrict__ dst,
                             int E) {
    __shared__ float Ws[DE * DH];  // 12 KB, layout [k][c]
    for (int i = threadIdx.x; i < DE * DH; i += blockDim.x) Ws[i] = We[i];
    __syncthreads();

    int lane = threadIdx.x & 31;
    int warp = blockIdx.x * (blockDim.x >> 5) + (threadIdx.x >> 5);
    int nwarps = gridDim.x * (blockDim.x >> 5);

    for (int e = warp; e < E; e += nwarps) {
        int s = __ldg(&src[e]);
        int d = __ldg(&dst[e]);
        float eav = ea[(size_t)e * DE + lane];  // coalesced 128B
        const float* xr = XM + (size_t)s * DH;
        float a0 = xr[lane], a1 = xr[lane + 32], a2 = xr[lane + 64];
#pragma unroll
        for (int k = 0; k < DE; k++) {
            float v = __shfl_sync(0xFFFFFFFFu, eav, k);
            a0 = fmaf(v, Ws[k * DH + lane],      a0);
            a1 = fmaf(v, Ws[k * DH + lane + 32], a1);
            a2 = fmaf(v, Ws[k * DH + lane + 64], a2);
        }
        unsigned* ag = g_AGG + (size_t)d * DH;
        atomicMax(ag + lane,      enc(a0));
        atomicMax(ag + lane + 32, enc(a1));
        atomicMax(ag + lane + 64, enc(a2));
    }
}

// out = leaky_relu( decode(AGG) + XR ); optionally reset AGG to sentinel.
__global__ void finalize(const float* __restrict__ XR,
                         float* __restrict__ out,
                         int n96, int reset) {
    int i = blockIdx.x * blockDim.x + threadIdx.x;
    int stride = gridDim.x * blockDim.x;
    for (; i < n96; i += stride) {
        unsigned u = g_AGG[i];
        float v = (u == SENT) ? 0.f : dec(u);
        if (reset) g_AGG[i] = SENT;
        float h = v + XR[i];
        out[i] = h > 0.f ? h : 0.01f * h;
    }
}

extern "C" void kernel_launch(void* const* d_in, const int* in_sizes, int n_in,
                              void* d_out, int out_size) {
    const float* X   = (const float*)d_in[0];
    const int*   ei  = (const int*)  d_in[1];
    const float* ea  = (const float*)d_in[2];
    const float* W1m = (const float*)d_in[3];
    const float* W1e = (const float*)d_in[4];
    const float* W1r = (const float*)d_in[5];
    const float* b1  = (const float*)d_in[6];
    const float* W2m = (const float*)d_in[7];
    const float* W2e = (const float*)d_in[8];
    const float* W2r = (const float*)d_in[9];
    const float* b2  = (const float*)d_in[10];

    int n = in_sizes[0] / DH;     // 50000
    int E = in_sizes[2] / DE;     // 800000
    const int* src = ei;
    const int* dst = ei + E;

    // Resolve scratch symbol addresses (no allocation; address lookup only)
    void *pXM, *pXR, *pC1;
    cudaGetSymbolAddress(&pXM, g_XM);
    cudaGetSymbolAddress(&pXR, g_XR);
    cudaGetSymbolAddress(&pC1, g_C1);
    float* XM = (float*)pXM;
    float* XR = (float*)pXR;
    float* C1 = (float*)pC1;

    const int SMEMW = 2 * DH * DH * (int)sizeof(float);  // 73728 B
    cudaFuncSetAttribute(node_gemm, cudaFuncAttributeMaxDynamicSharedMemorySize, SMEMW);

    dim3 gb(96, 4);
    int n96 = n * DH;

    init_agg<<<4736, 256>>>(n96);

    // Layer 1
    node_gemm<<<1480, gb, SMEMW>>>(X, W1m, W1r, b1, XM, XR, n);
    edge_scatter<<<1184, 256>>>(XM, ea, W1e, src, dst, E);
    finalize<<<4736, 256>>>(XR, C1, n96, /*reset=*/1);

    // Layer 2
    node_gemm<<<1480, gb, SMEMW>>>(C1, W2m, W2r, b2, XM, XR, n);
    edge_scatter<<<1184, 256>>>(XM, ea, W2e, src, dst, E);
    finalize<<<4736, 256>>>(XR, (float*)d_out, n96, /*reset=*/0);
}

// round 2
// speedup vs baseline: 1.3598x; 1.3598x over previous
#include <cuda_runtime.h>

#define DH 96
#define DE 32
#define NMAX 50000
#define EMAX 800000

// Scratch (static __device__ arrays — allocation-free per harness rules)
__device__ float g_XM[NMAX * DH];
__device__ float g_XR[NMAX * DH];
__device__ float g_C1[NMAX * DH];
__device__ int   g_cnt[NMAX];
__device__ int   g_off[NMAX + 1];
__device__ int   g_cur[NMAX];
__device__ int2  g_edges[EMAX];   // {src, eid} grouped by dst

// ---------------- CSR build ----------------
__global__ void zero_cnt(int n) {
    int i = blockIdx.x * blockDim.x + threadIdx.x;
    if (i < n) g_cnt[i] = 0;
}

__global__ void count_edges(const int* __restrict__ dst, int E) {
    int i = blockIdx.x * blockDim.x + threadIdx.x;
    int stride = gridDim.x * blockDim.x;
    for (; i < E; i += stride) atomicAdd(&g_cnt[dst[i]], 1);
}

// single-block exclusive scan of g_cnt -> g_off, g_cur
__global__ void scan_kernel(int n) {
    __shared__ int sdata[1024];
    __shared__ int carry_s;
    int tid = threadIdx.x;
    if (tid == 0) carry_s = 0;
    __syncthreads();
    for (int base = 0; base < n; base += 1024) {
        int i = base + tid;
        int v = (i < n) ? g_cnt[i] : 0;
        sdata[tid] = v;
        __syncthreads();
        for (int off = 1; off < 1024; off <<= 1) {
            int t = (tid >= off) ? sdata[tid - off] : 0;
            __syncthreads();
            sdata[tid] += t;
            __syncthreads();
        }
        int incl = sdata[tid];
        int excl = incl - v + carry_s;
        if (i < n) { g_off[i] = excl; g_cur[i] = excl; }
        __syncthreads();
        if (tid == 1023) carry_s += incl;
        __syncthreads();
    }
    if (tid == 0) g_off[n] = carry_s;
}

__global__ void fill_edges(const int* __restrict__ src,
                           const int* __restrict__ dst, int E) {
    int i = blockIdx.x * blockDim.x + threadIdx.x;
    int stride = gridDim.x * blockDim.x;
    for (; i < E; i += stride) {
        int pos = atomicAdd(&g_cur[dst[i]], 1);
        g_edges[pos] = make_int2(src[i], i);
    }
}

// ---------------- node GEMM: XM = in@Wm ; XR = in@Wr + b ----------------
extern __shared__ float smem_dyn[];
__global__ void node_gemm(const float* __restrict__ in,
                          const float* __restrict__ Wm,
                          const float* __restrict__ Wr,
                          const float* __restrict__ b,
                          float* __restrict__ XM,
                          float* __restrict__ XR,
                          int n) {
    float* Wms = smem_dyn;            // [96*96], layout [k][c]
    float* Wrs = smem_dyn + DH * DH;
    __shared__ float xs[4][DH];
    __shared__ float bs[DH];

    int tid = threadIdx.y * blockDim.x + threadIdx.x;  // 0..383
    for (int i = tid; i < DH * DH; i += 384) { Wms[i] = Wm[i]; Wrs[i] = Wr[i]; }
    if (tid < DH) bs[tid] = b[tid];
    __syncthreads();

    int tx = threadIdx.x, ty = threadIdx.y;
    int ngroups = (n + 3) >> 2;
    for (int g = blockIdx.x; g < ngroups; g += gridDim.x) {
        int row0 = g * 4;
        __syncthreads();
        {
            int r = tid / DH, k = tid % DH;
            int row = row0 + r;
            xs[r][k] = (row < n) ? in[(size_t)row * DH + k] : 0.f;
        }
        __syncthreads();
        int row = row0 + ty;
        if (row < n) {
            float am = 0.f, ar = 0.f;
#pragma unroll 8
            for (int k = 0; k < DH; k++) {
                float xv = xs[ty][k];
                am = fmaf(xv, Wms[k * DH + tx], am);
                ar = fmaf(xv, Wrs[k * DH + tx], ar);
            }
            XM[(size_t)row * DH + tx] = am;
            XR[(size_t)row * DH + tx] = ar + bs[tx];
        }
    }
}

// ---------------- fused gather-max + finalize ----------------
// One warp per dst node. We[32x96] lives in registers (3 cols per lane).
// out = leaky_relu( max_e(XM[src]+ea@We) [0 if no edges] + XR )
__global__ void __launch_bounds__(128, 4)
gather_max(const float* __restrict__ XM,
           const float* __restrict__ ea,
           const float* __restrict__ We,
           const float* __restrict__ XR,
           float* __restrict__ out,
           int n) {
    __shared__ float Ws[DE * DH];
    for (int i = threadIdx.x; i < DE * DH; i += 128) Ws[i] = We[i];
    __syncthreads();

    int lane = threadIdx.x & 31;
    float w0[DE], w1[DE], w2[DE];
#pragma unroll
    for (int k = 0; k < DE; k++) {
        w0[k] = Ws[k * DH + lane];
        w1[k] = Ws[k * DH + lane + 32];
        w2[k] = Ws[k * DH + lane + 64];
    }

    int warp = blockIdx.x * 4 + (threadIdx.x >> 5);
    int nwarps = gridDim.x * 4;

    for (int i = warp; i < n; i += nwarps) {
        int beg = g_off[i], end = g_off[i + 1];
        float m0 = -__builtin_huge_valf(), m1 = m0, m2 = m0;

        // software pipeline: prefetch edge j+1 while computing edge j
        float eav = 0.f, x0 = 0.f, x1 = 0.f, x2 = 0.f;
        if (beg < end) {
            int2 se = g_edges[beg];
            eav = ea[(size_t)se.y * DE + lane];
            const float* xp = XM + (size_t)se.x * DH;
            x0 = xp[lane]; x1 = xp[lane + 32]; x2 = xp[lane + 64];
        }
        for (int j = beg; j < end; j++) {
            float ce = eav, c0 = x0, c1 = x1, c2 = x2;
            if (j + 1 < end) {
                int2 sn = g_edges[j + 1];
                eav = ea[(size_t)sn.y * DE + lane];
                const float* xp = XM + (size_t)sn.x * DH;
                x0 = xp[lane]; x1 = xp[lane + 32]; x2 = xp[lane + 64];
            }
#pragma unroll
            for (int k = 0; k < DE; k++) {
                float v = __shfl_sync(0xFFFFFFFFu, ce, k);
                c0 = fmaf(v, w0[k], c0);
                c1 = fmaf(v, w1[k], c1);
                c2 = fmaf(v, w2[k], c2);
            }
            m0 = fmaxf(m0, c0);
            m1 = fmaxf(m1, c1);
            m2 = fmaxf(m2, c2);
        }
        if (beg == end) { m0 = 0.f; m1 = 0.f; m2 = 0.f; }

        size_t o = (size_t)i * DH;
        float h0 = m0 + XR[o + lane];
        float h1 = m1 + XR[o + lane + 32];
        float h2 = m2 + XR[o + lane + 64];
        out[o + lane]      = h0 > 0.f ? h0 : 0.01f * h0;
        out[o + lane + 32] = h1 > 0.f ? h1 : 0.01f * h1;
        out[o + lane + 64] = h2 > 0.f ? h2 : 0.01f * h2;
    }
}

extern "C" void kernel_launch(void* const* d_in, const int* in_sizes, int n_in,
                              void* d_out, int out_size) {
    const float* X   = (const float*)d_in[0];
    const int*   ei  = (const int*)  d_in[1];
    const float* ea  = (const float*)d_in[2];
    const float* W1m = (const float*)d_in[3];
    const float* W1e = (const float*)d_in[4];
    const float* W1r = (const float*)d_in[5];
    const float* b1  = (const float*)d_in[6];
    const float* W2m = (const float*)d_in[7];
    const float* W2e = (const float*)d_in[8];
    const float* W2r = (const float*)d_in[9];
    const float* b2  = (const float*)d_in[10];

    int n = in_sizes[0] / DH;     // 50000
    int E = in_sizes[2] / DE;     // 800000
    if (E > EMAX) E = EMAX;
    const int* src = ei;
    const int* dst = ei + E;

    void *pXM, *pXR, *pC1;
    cudaGetSymbolAddress(&pXM, g_XM);
    cudaGetSymbolAddress(&pXR, g_XR);
    cudaGetSymbolAddress(&pC1, g_C1);
    float* XM = (float*)pXM;
    float* XR = (float*)pXR;
    float* C1 = (float*)pC1;

    const int SMEMW = 2 * DH * DH * (int)sizeof(float);  // 73728 B
    cudaFuncSetAttribute(node_gemm, cudaFuncAttributeMaxDynamicSharedMemorySize, SMEMW);

    // --- CSR build (shared by both layers) ---
    zero_cnt<<<(n + 255) / 256, 256>>>(n);
    count_edges<<<1184, 256>>>(dst, E);
    scan_kernel<<<1, 1024>>>(n);
    fill_edges<<<1184, 256>>>(src, dst, E);

    dim3 gb(96, 4);

    // Layer 1
    node_gemm<<<1480, gb, SMEMW>>>(X, W1m, W1r, b1, XM, XR, n);
    gather_max<<<1184, 128>>>(XM, ea, W1e, XR, C1, n);

    // Layer 2
    node_gemm<<<1480, gb, SMEMW>>>(C1, W2m, W2r, b2, XM, XR, n);
    gather_max<<<1184, 128>>>(XM, ea, W2e, XR, (float*)d_out, n);
}

// round 4
// speedup vs baseline: 1.3599x; 1.0001x over previous
#include <cuda_runtime.h>

#define DH 96
#define DE 32
#define NMAX 50000
#define EMAX 800000

// Scratch (static __device__ arrays — allocation-free per harness rules)
__device__ float g_XM[NMAX * DH];
__device__ float g_XR[NMAX * DH];
__device__ float g_C1[NMAX * DH];
__device__ int   g_cnt[NMAX];
__device__ int   g_off[NMAX + 1];
__device__ int   g_cur[NMAX];
__device__ int2  g_edges[EMAX];   // {src, eid} grouped by dst

// ---------------- CSR build ----------------
__global__ void zero_cnt(int n) {
    int i = blockIdx.x * blockDim.x + threadIdx.x;
    if (i < n) g_cnt[i] = 0;
}

__global__ void count_edges(const int* __restrict__ dst, int E) {
    int i = blockIdx.x * blockDim.x + threadIdx.x;
    int stride = gridDim.x * blockDim.x;
    for (; i < E; i += stride) atomicAdd(&g_cnt[dst[i]], 1);
}

// single-block exclusive scan of g_cnt -> g_off, g_cur
__global__ void scan_kernel(int n) {
    __shared__ int sdata[1024];
    __shared__ int carry_s;
    int tid = threadIdx.x;
    if (tid == 0) carry_s = 0;
    __syncthreads();
    for (int base = 0; base < n; base += 1024) {
        int i = base + tid;
        int v = (i < n) ? g_cnt[i] : 0;
        sdata[tid] = v;
        __syncthreads();
        for (int off = 1; off < 1024; off <<= 1) {
            int t = (tid >= off) ? sdata[tid - off] : 0;
            __syncthreads();
            sdata[tid] += t;
            __syncthreads();
        }
        int incl = sdata[tid];
        int excl = incl - v + carry_s;
        if (i < n) { g_off[i] = excl; g_cur[i] = excl; }
        __syncthreads();
        if (tid == 1023) carry_s += incl;
        __syncthreads();
    }
    if (tid == 0) g_off[n] = carry_s;
}

__global__ void fill_edges(const int* __restrict__ src,
                           const int* __restrict__ dst, int E) {
    int i = blockIdx.x * blockDim.x + threadIdx.x;
    int stride = gridDim.x * blockDim.x;
    for (; i < E; i += stride) {
        int pos = atomicAdd(&g_cur[dst[i]], 1);
        g_edges[pos] = make_int2(src[i], i);
    }
}

// ---------------- node GEMM: XM = in@Wm ; XR = in@Wr + b ----------------
extern __shared__ float smem_dyn[];
__global__ void node_gemm(const float* __restrict__ in,
                          const float* __restrict__ Wm,
                          const float* __restrict__ Wr,
                          const float* __restrict__ b,
                          float* __restrict__ XM,
                          float* __restrict__ XR,
                          int n) {
    float* Wms = smem_dyn;            // [96*96], layout [k][c]
    float* Wrs = smem_dyn + DH * DH;
    __shared__ float xs[4][DH];
    __shared__ float bs[DH];

    int tid = threadIdx.y * blockDim.x + threadIdx.x;  // 0..383
    for (int i = tid; i < DH * DH; i += 384) { Wms[i] = Wm[i]; Wrs[i] = Wr[i]; }
    if (tid < DH) bs[tid] = b[tid];
    __syncthreads();

    int tx = threadIdx.x, ty = threadIdx.y;
    int ngroups = (n + 3) >> 2;
    for (int g = blockIdx.x; g < ngroups; g += gridDim.x) {
        int row0 = g * 4;
        __syncthreads();
        {
            int r = tid / DH, k = tid % DH;
            int row = row0 + r;
            xs[r][k] = (row < n) ? in[(size_t)row * DH + k] : 0.f;
        }
        __syncthreads();
        int row = row0 + ty;
        if (row < n) {
            float am = 0.f, ar = 0.f;
#pragma unroll 8
            for (int k = 0; k < DH; k++) {
                float xv = xs[ty][k];
                am = fmaf(xv, Wms[k * DH + tx], am);
                ar = fmaf(xv, Wrs[k * DH + tx], ar);
            }
            XM[(size_t)row * DH + tx] = am;
            XR[(size_t)row * DH + tx] = ar + bs[tx];
        }
    }
}

// ---------------- fused gather-max + finalize ----------------
// One warp per dst node. We[32x96] lives in registers (3 cols per lane).
// out = leaky_relu( max_e(XM[src]+ea@We) [0 if no edges] + XR )
__global__ void __launch_bounds__(128, 4)
gather_max(const float* __restrict__ XM,
           const float* __restrict__ ea,
           const float* __restrict__ We,
           const float* __restrict__ XR,
           float* __restrict__ out,
           int n) {
    __shared__ float Ws[DE * DH];
    for (int i = threadIdx.x; i < DE * DH; i += 128) Ws[i] = We[i];
    __syncthreads();

    int lane = threadIdx.x & 31;
    float w0[DE], w1[DE], w2[DE];
#pragma unroll
    for (int k = 0; k < DE; k++) {
        w0[k] = Ws[k * DH + lane];
        w1[k] = Ws[k * DH + lane + 32];
        w2[k] = Ws[k * DH + lane + 64];
    }

    int warp = blockIdx.x * 4 + (threadIdx.x >> 5);
    int nwarps = gridDim.x * 4;

    for (int i = warp; i < n; i += nwarps) {
        int beg = g_off[i], end = g_off[i + 1];
        float m0 = -__builtin_huge_valf(), m1 = m0, m2 = m0;

        // software pipeline: prefetch edge j+1 while computing edge j
        float eav = 0.f, x0 = 0.f, x1 = 0.f, x2 = 0.f;
        if (beg < end) {
            int2 se = g_edges[beg];
            eav = ea[(size_t)se.y * DE + lane];
            const float* xp = XM + (size_t)se.x * DH;
            x0 = xp[lane]; x1 = xp[lane + 32]; x2 = xp[lane + 64];
        }
        for (int j = beg; j < end; j++) {
            float ce = eav, c0 = x0, c1 = x1, c2 = x2;
            if (j + 1 < end) {
                int2 sn = g_edges[j + 1];
                eav = ea[(size_t)sn.y * DE + lane];
                const float* xp = XM + (size_t)sn.x * DH;
                x0 = xp[lane]; x1 = xp[lane + 32]; x2 = xp[lane + 64];
            }
#pragma unroll
            for (int k = 0; k < DE; k++) {
                float v = __shfl_sync(0xFFFFFFFFu, ce, k);
                c0 = fmaf(v, w0[k], c0);
                c1 = fmaf(v, w1[k], c1);
                c2 = fmaf(v, w2[k], c2);
            }
            m0 = fmaxf(m0, c0);
            m1 = fmaxf(m1, c1);
            m2 = fmaxf(m2, c2);
        }
        if (beg == end) { m0 = 0.f; m1 = 0.f; m2 = 0.f; }

        size_t o = (size_t)i * DH;
        float h0 = m0 + XR[o + lane];
        float h1 = m1 + XR[o + lane + 32];
        float h2 = m2 + XR[o + lane + 64];
        out[o + lane]      = h0 > 0.f ? h0 : 0.01f * h0;
        out[o + lane + 32] = h1 > 0.f ? h1 : 0.01f * h1;
        out[o + lane + 64] = h2 > 0.f ? h2 : 0.01f * h2;
    }
}

extern "C" void kernel_launch(void* const* d_in, const int* in_sizes, int n_in,
                              void* d_out, int out_size) {
    const float* X   = (const float*)d_in[0];
    const int*   ei  = (const int*)  d_in[1];
    const float* ea  = (const float*)d_in[2];
    const float* W1m = (const float*)d_in[3];
    const float* W1e = (const float*)d_in[4];
    const float* W1r = (const float*)d_in[5];
    const float* b1  = (const float*)d_in[6];
    const float* W2m = (const float*)d_in[7];
    const float* W2e = (const float*)d_in[8];
    const float* W2r = (const float*)d_in[9];
    const float* b2  = (const float*)d_in[10];

    int n = in_sizes[0] / DH;     // 50000
    int E = in_sizes[2] / DE;     // 800000
    if (E > EMAX) E = EMAX;
    const int* src = ei;
    const int* dst = ei + E;

    void *pXM, *pXR, *pC1;
    cudaGetSymbolAddress(&pXM, g_XM);
    cudaGetSymbolAddress(&pXR, g_XR);
    cudaGetSymbolAddress(&pC1, g_C1);
    float* XM = (float*)pXM;
    float* XR = (float*)pXR;
    float* C1 = (float*)pC1;

    const int SMEMW = 2 * DH * DH * (int)sizeof(float);  // 73728 B
    cudaFuncSetAttribute(node_gemm, cudaFuncAttributeMaxDynamicSharedMemorySize, SMEMW);

    // --- CSR build (shared by both layers) ---
    zero_cnt<<<(n + 255) / 256, 256>>>(n);
    count_edges<<<1184, 256>>>(dst, E);
    scan_kernel<<<1, 1024>>>(n);
    fill_edges<<<1184, 256>>>(src, dst, E);

    dim3 gb(96, 4);

    // Layer 1
    node_gemm<<<1480, gb, SMEMW>>>(X, W1m, W1r, b1, XM, XR, n);
    gather_max<<<1184, 128>>>(XM, ea, W1e, XR, C1, n);

    // Layer 2
    node_gemm<<<1480, gb, SMEMW>>>(C1, W2m, W2r, b2, XM, XR, n);
    gather_max<<<1184, 128>>>(XM, ea, W2e, XR, (float*)d_out, n);
}